// round 6
// baseline (speedup 1.0000x reference)
#include <cuda_runtime.h>

#define B_   4
#define C_   64
#define H_   128
#define W_   128
#define O_   64
#define K2C  9
#define OFFC 18
#define HW   (H_*W_)

typedef unsigned long long ull;

__device__ float g_offset[B_ * OFFC * HW];   // [b][oc][h][w]
__device__ float g_wt[K2C * C_ * O_];        // [k2][c][o]
__device__ float g_xt[B_ * HW * C_];         // NHWC: [b][h][w][c]

// ---- packed fp32x2 helpers (Blackwell) -------------------------------------
__device__ __forceinline__ void ffma2(ull& d, ull a, ull b) {
    asm("fma.rn.f32x2 %0, %1, %2, %0;" : "+l"(d) : "l"(a), "l"(b));
}
__device__ __forceinline__ ull pack2(float s) {
    ull r;
    asm("mov.b64 %0, {%1, %1};" : "=l"(r) : "f"(s));
    return r;
}
__device__ __forceinline__ float2 unpack2(ull v) {
    float2 f;
    asm("mov.b64 {%0, %1}, %2;" : "=f"(f.x), "=f"(f.y) : "l"(v));
    return f;
}

// ---------------------------------------------------------------------------
// Kernel 0: NCHW -> NHWC transpose of x.
// ---------------------------------------------------------------------------
__global__ void __launch_bounds__(256) transpose_x_kernel(const float* __restrict__ x)
{
    __shared__ float tile[32][33];
    const int bh = blockIdx.z;
    const int b  = bh >> 7;
    const int h  = bh & 127;
    const int w0 = blockIdx.x * 32;
    const int c0 = blockIdx.y * 32;
    const int tx = threadIdx.x;        // 0..31
    const int ty = threadIdx.y;        // 0..7

#pragma unroll
    for (int k = 0; k < 4; k++) {
        int c = c0 + ty + 8 * k;
        tile[ty + 8 * k][tx] = x[((size_t)(b * C_ + c) * H_ + h) * W_ + w0 + tx];
    }
    __syncthreads();
#pragma unroll
    for (int k = 0; k < 4; k++) {
        int w = w0 + ty + 8 * k;
        g_xt[((size_t)(b * H_ + h) * W_ + w) * C_ + c0 + tx] = tile[tx][ty + 8 * k];
    }
}

// ---------------------------------------------------------------------------
// Kernel 1: offset conv (3x3, 64 -> 18, pad 1). Unchanged from R5.
// ---------------------------------------------------------------------------
__global__ void __launch_bounds__(256, 2) offset_conv_kernel(
    const float* __restrict__ x,
    const float* __restrict__ w_off,
    const float* __restrict__ b_off)
{
    __shared__ float ws[C_ * K2C * 20];
    __shared__ ull   red[3][9][128];

    const int t = threadIdx.x;
    for (int i = t; i < C_ * K2C * 20; i += 256) {
        int rem = i % 20;
        int ck  = i / 20;
        float v = 0.f;
        if (rem < OFFC) {
            int c = ck / K2C, k = ck % K2C;
            v = w_off[(rem * C_ + c) * K2C + k];
        }
        ws[i] = v;
    }
    __syncthreads();

    const int pp    = t & 63;
    const int chunk = t >> 6;
    const int wo0   = pp * 2;
    const int ho    = blockIdx.x;
    const int b     = blockIdx.y;

    ull acc0[10], acc1[10];
#pragma unroll
    for (int i = 0; i < 10; i++) { acc0[i] = 0ull; acc1[i] = 0ull; }

    bool rv[3]; int rbase[3];
#pragma unroll
    for (int r = 0; r < 3; r++) {
        int yy = ho + r - 1;
        rv[r] = (yy >= 0) & (yy < H_);
        rbase[r] = yy * W_;
    }
    const bool s0v = (wo0 >= 2);
    const bool s2v = (wo0 <= W_ - 4);

    const float* xb = x + (size_t)b * C_ * HW;
    const int c0 = chunk * 16;
    for (int c = c0; c < c0 + 16; c++) {
        const float* xc = xb + c * HW;
        float f[3][6];
#pragma unroll
        for (int r = 0; r < 3; r++) {
            float2 a = make_float2(0.f, 0.f);
            float2 m = make_float2(0.f, 0.f);
            float2 e = make_float2(0.f, 0.f);
            if (rv[r]) {
                if (s0v) a = __ldg((const float2*)(xc + rbase[r] + wo0 - 2));
                m = __ldg((const float2*)(xc + rbase[r] + wo0));
                if (s2v) e = __ldg((const float2*)(xc + rbase[r] + wo0 + 2));
            }
            f[r][0] = a.x; f[r][1] = a.y;
            f[r][2] = m.x; f[r][3] = m.y;
            f[r][4] = e.x; f[r][5] = e.y;
        }
#pragma unroll
        for (int k = 0; k < K2C; k++) {
            int r = k / 3, kw = k % 3;
            ull s0 = pack2(f[r][1 + kw]);
            ull s1 = pack2(f[r][2 + kw]);
            const ulonglong2* wp = (const ulonglong2*)(ws + (c * K2C + k) * 20);
#pragma unroll
            for (int q = 0; q < 5; q++) {
                ulonglong2 w = wp[q];
                ffma2(acc0[2 * q + 0], s0, w.x);
                ffma2(acc0[2 * q + 1], s0, w.y);
                ffma2(acc1[2 * q + 0], s1, w.x);
                ffma2(acc1[2 * q + 1], s1, w.y);
            }
        }
    }

    if (chunk != 0) {
#pragma unroll
        for (int j = 0; j < 9; j++) {
            red[chunk - 1][j][wo0]     = acc0[j];
            red[chunk - 1][j][wo0 + 1] = acc1[j];
        }
    }
    __syncthreads();
    if (chunk == 0) {
        float* op = g_offset + ((size_t)(b * OFFC) * H_ + ho) * W_ + wo0;
#pragma unroll
        for (int j = 0; j < 9; j++) {
            float2 a0 = unpack2(acc0[j]);
            float2 a1 = unpack2(acc1[j]);
            float2 p10 = unpack2(red[0][j][wo0]);
            float2 p11 = unpack2(red[0][j][wo0 + 1]);
            float2 p20 = unpack2(red[1][j][wo0]);
            float2 p21 = unpack2(red[1][j][wo0 + 1]);
            float2 p30 = unpack2(red[2][j][wo0]);
            float2 p31 = unpack2(red[2][j][wo0 + 1]);
            float bx = __ldg(b_off + 2 * j + 0);
            float by = __ldg(b_off + 2 * j + 1);
            op[(size_t)(2 * j + 0) * HW]     = (a0.x + p10.x) + (p20.x + p30.x) + bx;
            op[(size_t)(2 * j + 0) * HW + 1] = (a1.x + p11.x) + (p21.x + p31.x) + bx;
            op[(size_t)(2 * j + 1) * HW]     = (a0.y + p10.y) + (p20.y + p30.y) + by;
            op[(size_t)(2 * j + 1) * HW + 1] = (a1.y + p11.y) + (p21.y + p31.y) + by;
        }
    }
}

// ---------------------------------------------------------------------------
// Kernel 2: transpose DCN weights [O][C][K2] -> [K2][C][O].
// ---------------------------------------------------------------------------
__global__ void transpose_w_kernel(const float* __restrict__ w_dcn)
{
    int i = blockIdx.x * 256 + threadIdx.x;
    if (i < O_ * C_ * K2C) {
        int o  = i / (C_ * K2C);
        int r  = i % (C_ * K2C);
        int c  = r / K2C;
        int k2 = r % K2C;
        g_wt[(k2 * C_ + c) * O_ + o] = w_dcn[i];
    }
}

// ---------------------------------------------------------------------------
// Kernel 3: deformable conv, NHWC sampling + pipelined f32x2 GEMM.
// Block = 256 px (2 rows), 256 threads.
// Sampling: warp w owns px w*32..w*32+31; per (px, tap, 32-ch half) the warp
// does lane=channel: 4 coalesced 128B LDG + bilinear, STS into smp (pad 257,
// conflict-free). Per-tap meta precomputed: float4 weights (validity folded)
// + corners packed into one int (o00 | dx<<14 | dy<<15).
// GEMM: 8 warps = 4 oc-groups x 2 px-groups, thread tile 4 px x 16 oc.
// ---------------------------------------------------------------------------
__global__ void __launch_bounds__(256, 2) deform_kernel(
    const float* __restrict__ b_dcn,
    float* __restrict__ out)
{
    __shared__ float  ws[2][C_ * O_];       // 32 KB
    __shared__ float  smp[2][32][257];      // 64.25 KB
    __shared__ float4 meta_w[2][256];       // 8 KB
    __shared__ int    meta_o[2][256];       // 2 KB

    const int t     = threadIdx.x;
    const int lane  = t & 31;
    const int warp  = t >> 5;
    const int ocg   = warp & 3;
    const int pxg   = warp >> 2;
    const int pbase = 128 * pxg + lane;
    const int ho0   = blockIdx.x * 2;
    const int b     = blockIdx.y;

    const float* xtb = g_xt + (size_t)b * HW * C_;

    // --- per-tap meta: 256 threads, one pixel each ---
    auto meta_compute = [&](int mbuf, int k2) {
        int p  = t;
        int ho = ho0 + (p >> 7);
        int wo = p & 127;
        const float* ob = g_offset + ((size_t)(b * OFFC + 2 * k2) * H_ + ho) * W_ + wo;
        float oy = __ldg(ob);
        float ox = __ldg(ob + HW);
        float py = (float)(ho - 1 + k2 / 3) + oy;
        float px = (float)(wo - 1 + k2 % 3) + ox;
        float y0f = floorf(py), x0f = floorf(px);
        float wy = py - y0f, wx = px - x0f;
        int y0 = (int)y0f, x0 = (int)x0f;
        float vy0 = ((y0 >= 0)  & (y0 < H_))     ? 1.f : 0.f;
        float vy1 = ((y0 >= -1) & (y0 < H_ - 1)) ? 1.f : 0.f;
        float vx0 = ((x0 >= 0)  & (x0 < W_))     ? 1.f : 0.f;
        float vx1 = ((x0 >= -1) & (x0 < W_ - 1)) ? 1.f : 0.f;
        float4 w4;
        w4.x = (1.f - wy) * (1.f - wx) * vy0 * vx0;
        w4.y = (1.f - wy) * wx         * vy0 * vx1;
        w4.z = wy * (1.f - wx)         * vy1 * vx0;
        w4.w = wy * wx                 * vy1 * vx1;
        int y0c = min(max(y0, 0), H_ - 1);
        int y1c = min(max(y0 + 1, 0), H_ - 1);
        int x0c = min(max(x0, 0), W_ - 1);
        int x1c = min(max(x0 + 1, 0), W_ - 1);
        int o00 = y0c * W_ + x0c;
        int dx  = x1c - x0c;               // 0 or 1
        int dy  = y1c - y0c;               // 0 or 1
        meta_w[mbuf][p] = w4;
        meta_o[mbuf][p] = o00 | (dx << 14) | (dy << 15);
    };

    // --- stage weight slice for tap k2 (16 KB coalesced) ---
    auto stage_ws = [&](int wbuf, int k2) {
        const float4* src = (const float4*)(g_wt + k2 * C_ * O_);
        float4* dst = (float4*)ws[wbuf];
#pragma unroll
        for (int q = 0; q < 4; q++)
            dst[t + q * 256] = src[t + q * 256];
    };

    // --- sampling: warp covers px warp*32..+31, lane = channel of half ch ---
    auto sample = [&](int sbuf, int mbuf, int ch) {
        const float* cb = xtb + ch * 32 + lane;
#pragma unroll 4
        for (int j = 0; j < 32; j++) {
            int p = warp * 32 + j;
            float4 w4 = meta_w[mbuf][p];
            int m = meta_o[mbuf][p];
            int o00 = m & 16383;
            int dx  = (m >> 14) & 1;
            int o10 = o00 + (((m >> 15) & 1) << 7);   // + dy*W
            float v00 = __ldg(cb + (size_t)o00 * C_);
            float v01 = __ldg(cb + (size_t)(o00 + dx) * C_);
            float v10 = __ldg(cb + (size_t)o10 * C_);
            float v11 = __ldg(cb + (size_t)(o10 + dx) * C_);
            smp[sbuf][lane][p] = v00 * w4.x + v01 * w4.y + v10 * w4.z + v11 * w4.w;
        }
    };

    ull acc[4][8];
#pragma unroll
    for (int i = 0; i < 4; i++)
#pragma unroll
        for (int j = 0; j < 8; j++) acc[i][j] = 0ull;

    // prologue: meta for tap0, weights tap0; then first sample
    meta_compute(0, 0);
    stage_ws(0, 0);
    __syncthreads();
    sample(0, 0, 0);
    __syncthreads();

    for (int it = 0; it < 18; it++) {
        const int buf = it & 1;
        const int k2  = it >> 1;
        const int ch  = it & 1;

        if (it < 17) {
            int nk2 = (it + 1) >> 1, nch = (it + 1) & 1;
            if (nch == 0) stage_ws(nk2 & 1, nk2);                 // it odd
            if (nch == 1 && nk2 + 1 <= 8)
                meta_compute((nk2 + 1) & 1, nk2 + 1);             // it even
            sample(buf ^ 1, nk2 & 1, nch);
        }

        // f32x2 GEMM over 32-channel half ch of tap k2
        {
            const float* wsl = ws[k2 & 1] + (ch * 32) * O_ + ocg * 16;
#pragma unroll 4
            for (int cl = 0; cl < 32; cl++) {
                const ulonglong2* wp = (const ulonglong2*)(wsl + cl * O_);
                ulonglong2 wA = wp[0], wB = wp[1], wC = wp[2], wD = wp[3];
#pragma unroll
                for (int i = 0; i < 4; i++) {
                    ull s = pack2(smp[buf][cl][pbase + 32 * i]);
                    ffma2(acc[i][0], s, wA.x); ffma2(acc[i][1], s, wA.y);
                    ffma2(acc[i][2], s, wB.x); ffma2(acc[i][3], s, wB.y);
                    ffma2(acc[i][4], s, wC.x); ffma2(acc[i][5], s, wC.y);
                    ffma2(acc[i][6], s, wD.x); ffma2(acc[i][7], s, wD.y);
                }
            }
        }
        __syncthreads();
    }

    // epilogue
#pragma unroll
    for (int i = 0; i < 4; i++) {
        int p  = pbase + 32 * i;
        int ho = ho0 + (p >> 7);
        int wo = p & 127;
#pragma unroll
        for (int j = 0; j < 8; j++) {
            float2 v = unpack2(acc[i][j]);
            int o = ocg * 16 + 2 * j;
            out[(((size_t)b * O_ + o)     * H_ + ho) * W_ + wo] = v.x + __ldg(b_dcn + o);
            out[(((size_t)b * O_ + o + 1) * H_ + ho) * W_ + wo] = v.y + __ldg(b_dcn + o + 1);
        }
    }
}

// ---------------------------------------------------------------------------
extern "C" void kernel_launch(void* const* d_in, const int* in_sizes, int n_in,
                              void* d_out, int out_size)
{
    const float* x     = (const float*)d_in[0];
    const float* w_off = (const float*)d_in[1];
    const float* b_off = (const float*)d_in[2];
    const float* w_dcn = (const float*)d_in[3];
    const float* b_dcn = (const float*)d_in[4];
    float* out = (float*)d_out;

    transpose_x_kernel<<<dim3(4, 2, B_ * H_), dim3(32, 8)>>>(x);
    offset_conv_kernel<<<dim3(H_, B_), 256>>>(x, w_off, b_off);
    transpose_w_kernel<<<(O_ * C_ * K2C + 255) / 256, 256>>>(w_dcn);
    deform_kernel<<<dim3(H_ / 2, B_), 256>>>(b_dcn, out);
}

// round 7
// speedup vs baseline: 1.1564x; 1.1564x over previous
#include <cuda_runtime.h>

#define B_   4
#define C_   64
#define H_   128
#define W_   128
#define O_   64
#define K2C  9
#define OFFC 18
#define HW   (H_*W_)

typedef unsigned long long ull;

__device__ float g_offset[B_ * OFFC * HW];   // [b][oc][h][w]
__device__ float g_wt[K2C * C_ * O_];        // [k2][c][o]

// ---- packed fp32x2 helpers (Blackwell) -------------------------------------
__device__ __forceinline__ void ffma2(ull& d, ull a, ull b) {
    asm("fma.rn.f32x2 %0, %1, %2, %0;" : "+l"(d) : "l"(a), "l"(b));
}
__device__ __forceinline__ ull addf2(ull a, ull b) {
    ull r;
    asm("add.rn.f32x2 %0, %1, %2;" : "=l"(r) : "l"(a), "l"(b));
    return r;
}
__device__ __forceinline__ ull pack2(float s) {
    ull r;
    asm("mov.b64 %0, {%1, %1};" : "=l"(r) : "f"(s));
    return r;
}
__device__ __forceinline__ float2 unpack2(ull v) {
    float2 f;
    asm("mov.b64 {%0, %1}, %2;" : "=f"(f.x), "=f"(f.y) : "l"(v));
    return f;
}

// ---------------------------------------------------------------------------
// Kernel 1: offset conv (3x3, 64 -> 18, pad 1).
// 256 threads = 64 pixel-pairs (t>>2) x 4 channel-chunks (t&3, 16 ch each).
// Chunks live in adjacent lanes -> cross-chunk reduction is 2 butterfly
// shuffles (no smem partials, no extra barrier). Weight smem is laid out
// [chunk][ci][k][20] with an 8-word chunk pad so the 4 distinct LDS.128
// addresses per warp hit disjoint bank groups (conflict-free).
// ---------------------------------------------------------------------------
#define WCH_STRIDE 2888   // 16*9*20 + 8 pad words; 2888 % 32 == 8

__global__ void __launch_bounds__(256, 3) offset_conv_kernel(
    const float* __restrict__ x,
    const float* __restrict__ w_off,
    const float* __restrict__ b_off)
{
    __shared__ float ws[4 * WCH_STRIDE];   // 46.2 KB

    const int t = threadIdx.x;
    for (int i = t; i < 4 * WCH_STRIDE; i += 256) {
        int chunk = i / WCH_STRIDE;
        int r     = i % WCH_STRIDE;
        float v = 0.f;
        if (r < 2880) {
            int ci = r / 180;
            int k  = (r % 180) / 20;
            int q  = r % 20;
            if (q < OFFC) {
                int c = chunk * 16 + ci;
                v = w_off[(q * C_ + c) * K2C + k];
            }
        }
        ws[i] = v;
    }
    __syncthreads();

    const int pp    = t >> 2;             // pixel pair 0..63
    const int chunk = t & 3;              // channel chunk (lane bits!)
    const int wo0   = pp * 2;
    const int ho    = blockIdx.x;
    const int b     = blockIdx.y;

    ull acc0[10], acc1[10];
#pragma unroll
    for (int i = 0; i < 10; i++) { acc0[i] = 0ull; acc1[i] = 0ull; }

    bool rv[3]; int rbase[3];
#pragma unroll
    for (int r = 0; r < 3; r++) {
        int yy = ho + r - 1;
        rv[r] = (yy >= 0) & (yy < H_);
        rbase[r] = yy * W_;
    }
    const bool s0v = (wo0 >= 2);
    const bool s2v = (wo0 <= W_ - 4);

    const float* xb = x + (size_t)b * C_ * HW;
    const float* wchunk = ws + chunk * WCH_STRIDE;

#pragma unroll 2
    for (int ci = 0; ci < 16; ci++) {
        const int c = chunk * 16 + ci;
        const float* xc = xb + c * HW;
        float f[3][6];
#pragma unroll
        for (int r = 0; r < 3; r++) {
            float2 a = make_float2(0.f, 0.f);
            float2 m = make_float2(0.f, 0.f);
            float2 e = make_float2(0.f, 0.f);
            if (rv[r]) {
                if (s0v) a = __ldg((const float2*)(xc + rbase[r] + wo0 - 2));
                m = __ldg((const float2*)(xc + rbase[r] + wo0));
                if (s2v) e = __ldg((const float2*)(xc + rbase[r] + wo0 + 2));
            }
            f[r][0] = a.x; f[r][1] = a.y;
            f[r][2] = m.x; f[r][3] = m.y;
            f[r][4] = e.x; f[r][5] = e.y;
        }
#pragma unroll
        for (int k = 0; k < K2C; k++) {
            int r = k / 3, kw = k % 3;
            ull s0 = pack2(f[r][1 + kw]);
            ull s1 = pack2(f[r][2 + kw]);
            const ulonglong2* wp = (const ulonglong2*)(wchunk + ci * 180 + k * 20);
#pragma unroll
            for (int q = 0; q < 5; q++) {
                ulonglong2 w = wp[q];
                ffma2(acc0[2 * q + 0], s0, w.x);
                ffma2(acc0[2 * q + 1], s0, w.y);
                ffma2(acc1[2 * q + 0], s1, w.x);
                ffma2(acc1[2 * q + 1], s1, w.y);
            }
        }
    }

    // butterfly reduction across the 4 chunk-lanes
#pragma unroll
    for (int j = 0; j < 9; j++) {
        acc0[j] = addf2(acc0[j], __shfl_xor_sync(0xffffffffu, acc0[j], 1));
        acc0[j] = addf2(acc0[j], __shfl_xor_sync(0xffffffffu, acc0[j], 2));
        acc1[j] = addf2(acc1[j], __shfl_xor_sync(0xffffffffu, acc1[j], 1));
        acc1[j] = addf2(acc1[j], __shfl_xor_sync(0xffffffffu, acc1[j], 2));
    }

    // distribute the 9 stores across the 4 chunk-lanes (chunk j-sets: 2 each,
    // chunk 0 also takes j=8)
    float* op = g_offset + ((size_t)(b * OFFC) * H_ + ho) * W_ + wo0;
#pragma unroll
    for (int j = 0; j < 9; j++) {
        bool mine = (j < 8) ? ((j >> 1) == chunk) : (chunk == 0);
        if (mine) {
            float2 a0 = unpack2(acc0[j]);
            float2 a1 = unpack2(acc1[j]);
            float bx = __ldg(b_off + 2 * j + 0);
            float by = __ldg(b_off + 2 * j + 1);
            op[(size_t)(2 * j + 0) * HW]     = a0.x + bx;
            op[(size_t)(2 * j + 0) * HW + 1] = a1.x + bx;
            op[(size_t)(2 * j + 1) * HW]     = a0.y + by;
            op[(size_t)(2 * j + 1) * HW + 1] = a1.y + by;
        }
    }
}

// ---------------------------------------------------------------------------
// Kernel 2: transpose DCN weights [O][C][K2] -> [K2][C][O].
// ---------------------------------------------------------------------------
__global__ void transpose_w_kernel(const float* __restrict__ w_dcn)
{
    int i = blockIdx.x * 256 + threadIdx.x;
    if (i < O_ * C_ * K2C) {
        int o  = i / (C_ * K2C);
        int r  = i % (C_ * K2C);
        int c  = r / K2C;
        int k2 = r % K2C;
        g_wt[(k2 * C_ + c) * O_ + o] = w_dcn[i];
    }
}

// ---------------------------------------------------------------------------
// Kernel 3: deformable conv, pipelined (R5 structure, new GEMM tiling).
// Block = 256 px (2 rows), 256 threads.
// Sampling (R5): warp (ocg=warp&3, pxg=warp>>2), thread covers 4 px x 8 ch,
//   scattered-but-coalesced NCHW gathers, validity folded into weights.
// GEMM: thread tile = 16 contiguous px x 4 oc, f32x2 packed over PIXEL PAIRS.
//   Per channel: 4 LDS.128 (16 samples) + 1 LDS.128 (4 weights) + 4 pack2
//   feeding 32 FFMA2 (5 LDS/ch vs 8 before).
// smp rows padded to 260 floats (16B-aligned rows, conflict-free STS).
// ---------------------------------------------------------------------------
__global__ void __launch_bounds__(256, 2) deform_kernel(
    const float* __restrict__ x,
    const float* __restrict__ b_dcn,
    float* __restrict__ out)
{
    __shared__ float ws[2][C_ * O_];      // 32 KB, double-buffered per k2
    __shared__ float smp[2][32][260];     // 65 KB, double-buffered per half

    const int t     = threadIdx.x;
    const int lane  = t & 31;
    const int warp  = t >> 5;
    // sampling mapping
    const int s_ocg = warp & 3;
    const int s_pxg = warp >> 2;
    const int pbase = 128 * s_pxg + lane;
    // GEMM mapping
    const int ob     = (t & 15) * 4;      // 4 output channels
    const int pxbase = (t >> 4) * 16;     // 16 contiguous pixels
    const int ho0   = blockIdx.x * 2;
    const int b     = blockIdx.y;

    const float* xb = x + (size_t)b * C_ * HW;

    auto stage_ws = [&](int wbuf, int k2) {
        const float4* src = (const float4*)(g_wt + k2 * C_ * O_);
        float4* dst = (float4*)ws[wbuf];
#pragma unroll
        for (int q = 0; q < 4; q++)
            dst[t + q * 256] = src[t + q * 256];
    };

    auto sample = [&](int sbuf, int k2, int ch) {
#pragma unroll
        for (int i = 0; i < 4; i++) {
            int p  = pbase + 32 * i;
            int ho = ho0 + (p >> 7);
            int wo = p & 127;
            const float* obp =
                g_offset + ((size_t)(b * OFFC + 2 * k2) * H_ + ho) * W_ + wo;
            float oy = __ldg(obp);
            float ox = __ldg(obp + HW);
            float py = (float)(ho - 1 + k2 / 3) + oy;
            float px = (float)(wo - 1 + k2 % 3) + ox;
            float y0f = floorf(py), x0f = floorf(px);
            float wy = py - y0f, wx = px - x0f;
            int y0 = (int)y0f, x0 = (int)x0f;
            float vy0 = ((y0 >= 0)  & (y0 < H_))     ? 1.f : 0.f;
            float vy1 = ((y0 >= -1) & (y0 < H_ - 1)) ? 1.f : 0.f;
            float vx0 = ((x0 >= 0)  & (x0 < W_))     ? 1.f : 0.f;
            float vx1 = ((x0 >= -1) & (x0 < W_ - 1)) ? 1.f : 0.f;
            float w00 = (1.f - wy) * (1.f - wx) * vy0 * vx0;
            float w01 = (1.f - wy) * wx         * vy0 * vx1;
            float w10 = wy * (1.f - wx)         * vy1 * vx0;
            float w11 = wy * wx                 * vy1 * vx1;
            int y0c = min(max(y0, 0), H_ - 1);
            int y1c = min(max(y0 + 1, 0), H_ - 1);
            int x0c = min(max(x0, 0), W_ - 1);
            int x1c = min(max(x0 + 1, 0), W_ - 1);
            int o00 = y0c * W_ + x0c;
            int o01 = y0c * W_ + x1c;
            int o10 = y1c * W_ + x0c;
            int o11 = y1c * W_ + x1c;
#pragma unroll
            for (int j = 0; j < 8; j++) {
                int cl = s_ocg * 8 + j;
                const float* xc = xb + (ch * 32 + cl) * HW;
                float s = __ldg(xc + o00) * w00 + __ldg(xc + o01) * w01
                        + __ldg(xc + o10) * w10 + __ldg(xc + o11) * w11;
                smp[sbuf][cl][p] = s;
            }
        }
    };

    ull acc[8][4];   // [px pair][oc]
#pragma unroll
    for (int i = 0; i < 8; i++)
#pragma unroll
        for (int j = 0; j < 4; j++) acc[i][j] = 0ull;

    stage_ws(0, 0);
    __syncthreads();   // ws[0] visible (also covers smem init ordering)
    sample(0, 0, 0);
    __syncthreads();

    for (int it = 0; it < 18; it++) {
        const int buf = it & 1;
        const int k2  = it >> 1;
        const int ch  = it & 1;

        if (it < 17) {
            int nk2 = (it + 1) >> 1, nch = (it + 1) & 1;
            if (nch == 0) stage_ws(nk2 & 1, nk2);
            sample(buf ^ 1, nk2, nch);
        }

        // f32x2 GEMM (px-pair packed) over 32-channel half ch of tap k2
        {
            const float* wsl = ws[k2 & 1] + (ch * 32) * O_ + ob;
#pragma unroll 4
            for (int cl = 0; cl < 32; cl++) {
                float4 wv = *(const float4*)(wsl + cl * O_);
                ull w0 = pack2(wv.x), w1 = pack2(wv.y);
                ull w2 = pack2(wv.z), w3 = pack2(wv.w);
                const ulonglong2* srow =
                    (const ulonglong2*)(&smp[buf][cl][pxbase]);
                ulonglong2 sA = srow[0];
                ulonglong2 sB = srow[1];
                ulonglong2 sC = srow[2];
                ulonglong2 sD = srow[3];
                ffma2(acc[0][0], sA.x, w0); ffma2(acc[0][1], sA.x, w1);
                ffma2(acc[0][2], sA.x, w2); ffma2(acc[0][3], sA.x, w3);
                ffma2(acc[1][0], sA.y, w0); ffma2(acc[1][1], sA.y, w1);
                ffma2(acc[1][2], sA.y, w2); ffma2(acc[1][3], sA.y, w3);
                ffma2(acc[2][0], sB.x, w0); ffma2(acc[2][1], sB.x, w1);
                ffma2(acc[2][2], sB.x, w2); ffma2(acc[2][3], sB.x, w3);
                ffma2(acc[3][0], sB.y, w0); ffma2(acc[3][1], sB.y, w1);
                ffma2(acc[3][2], sB.y, w2); ffma2(acc[3][3], sB.y, w3);
                ffma2(acc[4][0], sC.x, w0); ffma2(acc[4][1], sC.x, w1);
                ffma2(acc[4][2], sC.x, w2); ffma2(acc[4][3], sC.x, w3);
                ffma2(acc[5][0], sC.y, w0); ffma2(acc[5][1], sC.y, w1);
                ffma2(acc[5][2], sC.y, w2); ffma2(acc[5][3], sC.y, w3);
                ffma2(acc[6][0], sD.x, w0); ffma2(acc[6][1], sD.x, w1);
                ffma2(acc[6][2], sD.x, w2); ffma2(acc[6][3], sD.x, w3);
                ffma2(acc[7][0], sD.y, w0); ffma2(acc[7][1], sD.y, w1);
                ffma2(acc[7][2], sD.y, w2); ffma2(acc[7][3], sD.y, w3);
            }
        }
        __syncthreads();
    }

    // epilogue: px pairs are horizontally adjacent -> float2 stores
#pragma unroll
    for (int j = 0; j < 4; j++) {
        int o = ob + j;
        float bia = __ldg(b_dcn + o);
#pragma unroll
        for (int pp = 0; pp < 8; pp++) {
            int p  = pxbase + 2 * pp;
            int ho = ho0 + (p >> 7);
            int wo = p & 127;
            float2 v = unpack2(acc[pp][j]);
            v.x += bia; v.y += bia;
            *(float2*)(&out[(((size_t)b * O_ + o) * H_ + ho) * W_ + wo]) = v;
        }
    }
}

// ---------------------------------------------------------------------------
extern "C" void kernel_launch(void* const* d_in, const int* in_sizes, int n_in,
                              void* d_out, int out_size)
{
    const float* x     = (const float*)d_in[0];
    const float* w_off = (const float*)d_in[1];
    const float* b_off = (const float*)d_in[2];
    const float* w_dcn = (const float*)d_in[3];
    const float* b_dcn = (const float*)d_in[4];
    float* out = (float*)d_out;

    offset_conv_kernel<<<dim3(H_, B_), 256>>>(x, w_off, b_off);
    transpose_w_kernel<<<(O_ * C_ * K2C + 255) / 256, 256>>>(w_dcn);
    deform_kernel<<<dim3(H_ / 2, B_), 256>>>(x, b_dcn, out);
}